// round 4
// baseline (speedup 1.0000x reference)
#include <cuda_runtime.h>
#include <math.h>

#define NIMG 4
#define NCLS 19
#define HWPIX 589824            // 768*768
#define NTOT (NIMG * HWPIX)
#define IGN 255
#define EDGE_T 0.8f
#define PPT 8                   // pixels per thread
#define TPB 256
#define BPI (HWPIX / (TPB * PPT))   // 288 blocks per image

// ---------------- device-global scratch (no allocations allowed) ----------------
// Zero-initialized at module load (covers the first correctness call);
// k_final resets everything after producing the output so each graph replay
// starts clean.
__device__ double g_seg_sum[NIMG * NCLS];
__device__ double g_att_sum[NIMG * NCLS];
__device__ int    g_seg_cnt[NIMG * NCLS];
__device__ int    g_att_cnt[NIMG * NCLS];
__device__ double g_bce_pos, g_bce_neg;
__device__ int    g_pos, g_neg;

// ---------------- kernel 1: single fused pass ----------------
// Reads segin once; accumulates per-image/per-class nll sums & counts
// (weights are linear -> applied in finalize), plus BCE pos/neg partial sums.
__global__ void __launch_bounds__(TPB) k_fused(const float* __restrict__ segin,
                                               const float* __restrict__ edgein,
                                               const int* __restrict__ segmask,
                                               const int* __restrict__ emask) {
    int n   = blockIdx.x / BPI;
    int tid = threadIdx.x;
    int wid = tid >> 5;
    int lid = tid & 31;

    int local = (blockIdx.x % BPI) * (TPB * PPT) + tid * PPT;
    int p     = n * HWPIX + local;

    int4   t0 = *(const int4*)(segmask + p);
    int4   t1 = *(const int4*)(segmask + p + 4);
    float4 e0 = *(const float4*)(edgein + p);
    float4 e1 = *(const float4*)(edgein + p + 4);
    int4   m0 = *(const int4*)(emask + p);
    int4   m1 = *(const int4*)(emask + p + 4);

    int   tv[PPT] = {t0.x, t0.y, t0.z, t0.w, t1.x, t1.y, t1.z, t1.w};
    float ev[PPT] = {e0.x, e0.y, e0.z, e0.w, e1.x, e1.y, e1.z, e1.w};
    int   mv[PPT] = {m0.x, m0.y, m0.z, m0.w, m1.x, m1.y, m1.z, m1.w};

    int tcls[PPT];                               // clipped class for gather
#pragma unroll
    for (int i = 0; i < PPT; i++) tcls[i] = min(max(tv[i], 0), NCLS - 1);

    // ---- channel sweep: online sum-exp + target-logit select ----
    const float* sp = segin + (size_t)n * (size_t)NCLS * (size_t)HWPIX + (size_t)local;

    float s[PPT], xt[PPT];
#pragma unroll
    for (int i = 0; i < PPT; i++) { s[i] = 0.f; xt[i] = 0.f; }

#pragma unroll
    for (int c0 = 0; c0 < NCLS; c0 += 4) {
        float4 a[4][2];
#pragma unroll
        for (int j = 0; j < 4; j++) {
            int c = c0 + j;
            if (c < NCLS) {
                a[j][0] = *(const float4*)(sp + (size_t)c * HWPIX);
                a[j][1] = *(const float4*)(sp + (size_t)c * HWPIX + 4);
            }
        }
#pragma unroll
        for (int j = 0; j < 4; j++) {
            int c = c0 + j;
            if (c < NCLS) {
                float xv[PPT] = {a[j][0].x, a[j][0].y, a[j][0].z, a[j][0].w,
                                 a[j][1].x, a[j][1].y, a[j][1].z, a[j][1].w};
#pragma unroll
                for (int i = 0; i < PPT; i++) {
                    s[i] += __expf(xv[i]);
                    xt[i] = (c == tcls[i]) ? xv[i] : xt[i];
                }
            }
        }
    }

    // ---- per-pixel nll, att flag, BCE ----
    float nll[PPT], nllA[PPT];
    unsigned addC[PPT];
    int ec[PPT];
    float bce_p = 0.f, bce_n = 0.f;
    unsigned pn = 0;                              // pos in low 16, neg in high 16
#pragma unroll
    for (int i = 0; i < PPT; i++) {
        nll[i] = __logf(s[i]) - xt[i];            // -log_softmax[target]
        bool v   = (tv[i] != IGN);
        bool att = v && (ev[i] > EDGE_T);
        ec[i]   = v ? tcls[i] : 255;              // 255 never matches class loop
        nllA[i] = att ? nll[i] : 0.f;
        addC[i] = att ? 0x10001u : 1u;            // att count hi16, seg count lo16

        float xx = ev[i];
        float b  = fmaxf(xx, 0.f) - xx * (float)mv[i] + log1pf(__expf(-fabsf(xx)));
        if (mv[i] == 1) { bce_p += b; pn += 1u; }
        else if (mv[i] == 0) { bce_n += b; pn += 0x10000u; }
    }

    // ---- per-class register select + warp reduction (no per-pixel atomics) ----
    __shared__ float sh_ss[NCLS][8];
    __shared__ float sh_sa[NCLS][8];
    __shared__ unsigned sh_cc[NCLS][8];
    __shared__ float sh_bp[8], sh_bn[8];
    __shared__ unsigned sh_pn[8];

#pragma unroll
    for (int c = 0; c < NCLS; c++) {
        float ss = 0.f, sa = 0.f;
        unsigned cc = 0u;
#pragma unroll
        for (int i = 0; i < PPT; i++) {
            if (ec[i] == c) { ss += nll[i]; sa += nllA[i]; cc += addC[i]; }
        }
        for (int o = 16; o; o >>= 1) {
            ss += __shfl_down_sync(0xffffffffu, ss, o);
            sa += __shfl_down_sync(0xffffffffu, sa, o);
        }
        cc = __reduce_add_sync(0xffffffffu, cc);
        if (lid == 0) { sh_ss[c][wid] = ss; sh_sa[c][wid] = sa; sh_cc[c][wid] = cc; }
    }
    for (int o = 16; o; o >>= 1) {
        bce_p += __shfl_down_sync(0xffffffffu, bce_p, o);
        bce_n += __shfl_down_sync(0xffffffffu, bce_n, o);
    }
    pn = __reduce_add_sync(0xffffffffu, pn);
    if (lid == 0) { sh_bp[wid] = bce_p; sh_bn[wid] = bce_n; sh_pn[wid] = pn; }
    __syncthreads();

    // ---- block combine + global accumulation ----
    if (tid < NCLS) {
        float ss = 0.f, sa = 0.f; unsigned cc = 0u;
#pragma unroll
        for (int w = 0; w < 8; w++) { ss += sh_ss[tid][w]; sa += sh_sa[tid][w]; cc += sh_cc[tid][w]; }
        int gi = n * NCLS + tid;
        atomicAdd(&g_seg_sum[gi], (double)ss);
        atomicAdd(&g_att_sum[gi], (double)sa);
        atomicAdd(&g_seg_cnt[gi], (int)(cc & 0xffffu));
        atomicAdd(&g_att_cnt[gi], (int)(cc >> 16));
    } else if (tid == 32) {
        float bp = 0.f, bn = 0.f; unsigned c = 0u;
#pragma unroll
        for (int w = 0; w < 8; w++) { bp += sh_bp[w]; bn += sh_bn[w]; c += sh_pn[w]; }
        atomicAdd(&g_bce_pos, (double)bp);
        atomicAdd(&g_bce_neg, (double)bn);
        atomicAdd(&g_pos, (int)(c & 0xffffu));
        atomicAdd(&g_neg, (int)(c >> 16));
    }
}

// ---------------- kernel 2: apply weights, finalize, reset scratch ----------------
__global__ void k_final(float* out) {
    int i = threadIdx.x;
    if (i == 0) {
        double segl = 0.0, attl = 0.0;
        for (int n = 0; n < NIMG; n++) {
            double ssum = 0.0, asum = 0.0;
            for (int c = 0; c < NCLS; c++) {
                ssum += (double)g_seg_cnt[n * NCLS + c];
                asum += (double)g_att_cnt[n * NCLS + c];
            }
            double snum = 0.0, sden = 0.0, anum = 0.0, aden = 0.0;
            for (int c = 0; c < NCLS; c++) {
                int sc = g_seg_cnt[n * NCLS + c];
                int ac = g_att_cnt[n * NCLS + c];
                double ws = sc ? (2.0 - (double)sc / ssum) : 1.0;
                double wa = ac ? (2.0 - (double)ac / asum) : 1.0;
                snum += ws * g_seg_sum[n * NCLS + c];
                sden += ws * (double)sc;
                anum += wa * g_att_sum[n * NCLS + c];
                aden += wa * (double)ac;
            }
            segl += snum / sden;
            attl += anum / aden;
        }
        double p = (double)g_pos, nn = (double)g_neg, sm = p + nn;
        double bce = ((nn / sm) * g_bce_pos + (p / sm) * g_bce_neg) / (double)NTOT;
        out[0] = (float)(segl + 0.3 * bce + 0.1 * attl);
    }
    __syncthreads();
    // reset scratch for next graph replay
    if (i < NIMG * NCLS) {
        g_seg_sum[i] = 0.0; g_att_sum[i] = 0.0;
        g_seg_cnt[i] = 0;   g_att_cnt[i] = 0;
    }
    if (i == 0) { g_bce_pos = 0.0; g_bce_neg = 0.0; g_pos = 0; g_neg = 0; }
}

extern "C" void kernel_launch(void* const* d_in, const int* in_sizes, int n_in,
                              void* d_out, int out_size) {
    const float* segin   = (const float*)d_in[0];
    const float* edgein  = (const float*)d_in[1];
    const int*   segmask = (const int*)d_in[2];
    const int*   emask   = (const int*)d_in[3];

    k_fused<<<NIMG * BPI, TPB>>>(segin, edgein, segmask, emask);
    k_final<<<1, 128>>>((float*)d_out);
}

// round 5
// speedup vs baseline: 1.8305x; 1.8305x over previous
#include <cuda_runtime.h>
#include <math.h>

#define NIMG 4
#define NCLS 19
#define HWPIX 589824            // 768*768
#define NTOT (NIMG * HWPIX)
#define IGN 255
#define EDGE_T 0.8f
#define PPT 8                   // pixels per thread
#define TPB 256
#define BPI (HWPIX / (TPB * PPT))   // 288 blocks per image

// ---------------- device-global scratch (no allocations allowed) ----------------
// Zero-initialized at module load (covers the first correctness call);
// k_final resets everything after producing the output so each graph replay
// starts clean.
__device__ double g_seg_sum[NIMG * NCLS];
__device__ double g_att_sum[NIMG * NCLS];
__device__ int    g_seg_cnt[NIMG * NCLS];
__device__ int    g_att_cnt[NIMG * NCLS];
__device__ double g_bce_pos, g_bce_neg;
__device__ int    g_pos, g_neg;

// ---------------- kernel 1: single fused pass ----------------
// Reads segin once; accumulates per-image/per-class nll sums & counts
// (weights are linear -> applied in finalize), plus BCE pos/neg partial sums.
__global__ void __launch_bounds__(TPB) k_fused(const float* __restrict__ segin,
                                               const float* __restrict__ edgein,
                                               const int* __restrict__ segmask,
                                               const int* __restrict__ emask) {
    int n   = blockIdx.x / BPI;
    int tid = threadIdx.x;
    int wid = tid >> 5;
    int lid = tid & 31;

    int local = (blockIdx.x % BPI) * (TPB * PPT) + tid * PPT;
    int p     = n * HWPIX + local;

    int4   t0 = *(const int4*)(segmask + p);
    int4   t1 = *(const int4*)(segmask + p + 4);
    float4 e0 = *(const float4*)(edgein + p);
    float4 e1 = *(const float4*)(edgein + p + 4);
    int4   m0 = *(const int4*)(emask + p);
    int4   m1 = *(const int4*)(emask + p + 4);

    int   tv[PPT] = {t0.x, t0.y, t0.z, t0.w, t1.x, t1.y, t1.z, t1.w};
    float ev[PPT] = {e0.x, e0.y, e0.z, e0.w, e1.x, e1.y, e1.z, e1.w};
    int   mv[PPT] = {m0.x, m0.y, m0.z, m0.w, m1.x, m1.y, m1.z, m1.w};

    int tcls[PPT];                               // clipped class for gather
#pragma unroll
    for (int i = 0; i < PPT; i++) tcls[i] = min(max(tv[i], 0), NCLS - 1);

    // ---- channel sweep: online sum-exp + target-logit select ----
    const float* sp = segin + (size_t)n * (size_t)NCLS * (size_t)HWPIX + (size_t)local;

    float s[PPT], xt[PPT];
#pragma unroll
    for (int i = 0; i < PPT; i++) { s[i] = 0.f; xt[i] = 0.f; }

#pragma unroll
    for (int c0 = 0; c0 < NCLS; c0 += 4) {
        float4 a[4][2];
#pragma unroll
        for (int j = 0; j < 4; j++) {
            int c = c0 + j;
            if (c < NCLS) {
                a[j][0] = *(const float4*)(sp + (size_t)c * HWPIX);
                a[j][1] = *(const float4*)(sp + (size_t)c * HWPIX + 4);
            }
        }
#pragma unroll
        for (int j = 0; j < 4; j++) {
            int c = c0 + j;
            if (c < NCLS) {
                float xv[PPT] = {a[j][0].x, a[j][0].y, a[j][0].z, a[j][0].w,
                                 a[j][1].x, a[j][1].y, a[j][1].z, a[j][1].w};
#pragma unroll
                for (int i = 0; i < PPT; i++) {
                    s[i] += __expf(xv[i]);
                    xt[i] = (c == tcls[i]) ? xv[i] : xt[i];
                }
            }
        }
    }

    // ---- per-pixel nll, att flag, BCE ----
    float nll[PPT], nllA[PPT];
    unsigned addC[PPT];
    int ec[PPT];
    float bce_p = 0.f, bce_n = 0.f;
    unsigned pn = 0;                              // pos in low 16, neg in high 16
#pragma unroll
    for (int i = 0; i < PPT; i++) {
        nll[i] = __logf(s[i]) - xt[i];            // -log_softmax[target]
        bool v   = (tv[i] != IGN);
        bool att = v && (ev[i] > EDGE_T);
        ec[i]   = v ? tcls[i] : 255;              // 255 never matches class loop
        nllA[i] = att ? nll[i] : 0.f;
        addC[i] = att ? 0x10001u : 1u;            // att count hi16, seg count lo16

        float xx = ev[i];
        float b  = fmaxf(xx, 0.f) - xx * (float)mv[i] + log1pf(__expf(-fabsf(xx)));
        if (mv[i] == 1) { bce_p += b; pn += 1u; }
        else if (mv[i] == 0) { bce_n += b; pn += 0x10000u; }
    }

    // ---- per-class register select + warp reduction (no per-pixel atomics) ----
    __shared__ float sh_ss[NCLS][8];
    __shared__ float sh_sa[NCLS][8];
    __shared__ unsigned sh_cc[NCLS][8];
    __shared__ float sh_bp[8], sh_bn[8];
    __shared__ unsigned sh_pn[8];

#pragma unroll
    for (int c = 0; c < NCLS; c++) {
        float ss = 0.f, sa = 0.f;
        unsigned cc = 0u;
#pragma unroll
        for (int i = 0; i < PPT; i++) {
            if (ec[i] == c) { ss += nll[i]; sa += nllA[i]; cc += addC[i]; }
        }
        for (int o = 16; o; o >>= 1) {
            ss += __shfl_down_sync(0xffffffffu, ss, o);
            sa += __shfl_down_sync(0xffffffffu, sa, o);
        }
        cc = __reduce_add_sync(0xffffffffu, cc);
        if (lid == 0) { sh_ss[c][wid] = ss; sh_sa[c][wid] = sa; sh_cc[c][wid] = cc; }
    }
    for (int o = 16; o; o >>= 1) {
        bce_p += __shfl_down_sync(0xffffffffu, bce_p, o);
        bce_n += __shfl_down_sync(0xffffffffu, bce_n, o);
    }
    pn = __reduce_add_sync(0xffffffffu, pn);
    if (lid == 0) { sh_bp[wid] = bce_p; sh_bn[wid] = bce_n; sh_pn[wid] = pn; }
    __syncthreads();

    // ---- block combine + global accumulation ----
    if (tid < NCLS) {
        float ss = 0.f, sa = 0.f; unsigned cc = 0u;
#pragma unroll
        for (int w = 0; w < 8; w++) { ss += sh_ss[tid][w]; sa += sh_sa[tid][w]; cc += sh_cc[tid][w]; }
        int gi = n * NCLS + tid;
        atomicAdd(&g_seg_sum[gi], (double)ss);
        atomicAdd(&g_att_sum[gi], (double)sa);
        atomicAdd(&g_seg_cnt[gi], (int)(cc & 0xffffu));
        atomicAdd(&g_att_cnt[gi], (int)(cc >> 16));
    } else if (tid == 32) {
        float bp = 0.f, bn = 0.f; unsigned c = 0u;
#pragma unroll
        for (int w = 0; w < 8; w++) { bp += sh_bp[w]; bn += sh_bn[w]; c += sh_pn[w]; }
        atomicAdd(&g_bce_pos, (double)bp);
        atomicAdd(&g_bce_neg, (double)bn);
        atomicAdd(&g_pos, (int)(c & 0xffffu));
        atomicAdd(&g_neg, (int)(c >> 16));
    }
}

// ---------------- kernel 2: apply weights, finalize, reset scratch ----------------
// Parallel loads (the R3 version did ~300 dependent single-thread global loads
// at DRAM latency = 84us). Here: 128 threads batch-load everything into shared,
// 4 threads (one per image) do the 19-class math out of shared, thread 0 combines.
__global__ void __launch_bounds__(128) k_final(float* out) {
    __shared__ double s_ss[NIMG * NCLS];   // seg nll sums
    __shared__ double s_as[NIMG * NCLS];   // att nll sums
    __shared__ int    s_sc[NIMG * NCLS];
    __shared__ int    s_ac[NIMG * NCLS];
    __shared__ double s_img[NIMG][2];      // per-image {seg term, att term}
    __shared__ double s_bce[2];
    __shared__ int    s_pn[2];

    int i = threadIdx.x;
    if (i < NIMG * NCLS) {                 // 76 parallel load chains, MLP=4 each
        s_ss[i] = g_seg_sum[i];
        s_as[i] = g_att_sum[i];
        s_sc[i] = g_seg_cnt[i];
        s_ac[i] = g_att_cnt[i];
    }
    if (i == 96)  { s_bce[0] = g_bce_pos; s_bce[1] = g_bce_neg; }
    if (i == 97)  { s_pn[0] = g_pos; s_pn[1] = g_neg; }
    __syncthreads();

    if (i < NIMG) {                        // one thread per image
        double ssum = 0.0, asum = 0.0;
        for (int c = 0; c < NCLS; c++) {
            ssum += (double)s_sc[i * NCLS + c];
            asum += (double)s_ac[i * NCLS + c];
        }
        double snum = 0.0, sden = 0.0, anum = 0.0, aden = 0.0;
        for (int c = 0; c < NCLS; c++) {
            int sc = s_sc[i * NCLS + c];
            int ac = s_ac[i * NCLS + c];
            double ws = sc ? (2.0 - (double)sc / ssum) : 1.0;
            double wa = ac ? (2.0 - (double)ac / asum) : 1.0;
            snum += ws * s_ss[i * NCLS + c];
            sden += ws * (double)sc;
            anum += wa * s_as[i * NCLS + c];
            aden += wa * (double)ac;
        }
        s_img[i][0] = snum / sden;
        s_img[i][1] = anum / aden;
    }
    __syncthreads();

    if (i == 0) {
        double segl = 0.0, attl = 0.0;
        for (int n = 0; n < NIMG; n++) { segl += s_img[n][0]; attl += s_img[n][1]; }
        double p = (double)s_pn[0], nn = (double)s_pn[1], sm = p + nn;
        double bce = ((nn / sm) * s_bce[0] + (p / sm) * s_bce[1]) / (double)NTOT;
        out[0] = (float)(segl + 0.3 * bce + 0.1 * attl);
    }

    // reset scratch for next graph replay (parallel stores, fire-and-forget)
    if (i < NIMG * NCLS) {
        g_seg_sum[i] = 0.0; g_att_sum[i] = 0.0;
        g_seg_cnt[i] = 0;   g_att_cnt[i] = 0;
    }
    if (i == 96) { g_bce_pos = 0.0; g_bce_neg = 0.0; }
    if (i == 97) { g_pos = 0; g_neg = 0; }
}

extern "C" void kernel_launch(void* const* d_in, const int* in_sizes, int n_in,
                              void* d_out, int out_size) {
    const float* segin   = (const float*)d_in[0];
    const float* edgein  = (const float*)d_in[1];
    const int*   segmask = (const int*)d_in[2];
    const int*   emask   = (const int*)d_in[3];

    k_fused<<<NIMG * BPI, TPB>>>(segin, edgein, segmask, emask);
    k_final<<<1, 128>>>((float*)d_out);
}

// round 7
// speedup vs baseline: 2.2433x; 1.2255x over previous
#include <cuda_runtime.h>
#include <math.h>

#define NIMG 4
#define NCLS 19
#define HWPIX 589824            // 768*768
#define NTOT (NIMG * HWPIX)
#define IGN 255
#define EDGE_T 0.8f
#define PPT 8                   // pixels per thread
#define TPB 256
#define BPI (HWPIX / (TPB * PPT))   // 288 blocks per image
#define GRID (NIMG * BPI)           // 1152

// ---------------- device-global scratch (no allocations allowed) ----------------
// Zero-initialized at module load (covers the first correctness call);
// the last block resets everything after producing the output so each graph
// replay starts clean.
__device__ double g_seg_sum[NIMG * NCLS];
__device__ double g_att_sum[NIMG * NCLS];
__device__ int    g_seg_cnt[NIMG * NCLS];
__device__ int    g_att_cnt[NIMG * NCLS];
__device__ double g_bce_pos, g_bce_neg;
__device__ int    g_pos, g_neg;
__device__ unsigned g_done;

// ---------------- single fused kernel ----------------
// Reads segin once; accumulates per-image/per-class nll sums & counts
// (weights are linear -> applied by the last block), plus BCE partial sums.
__global__ void __launch_bounds__(TPB) k_fused(const float* __restrict__ segin,
                                               const float* __restrict__ edgein,
                                               const int* __restrict__ segmask,
                                               const int* __restrict__ emask,
                                               float* __restrict__ out) {
    int n   = blockIdx.x / BPI;
    int tid = threadIdx.x;
    int wid = tid >> 5;
    int lid = tid & 31;

    int local = (blockIdx.x % BPI) * (TPB * PPT) + tid * PPT;
    int p     = n * HWPIX + local;

    int4   t0 = *(const int4*)(segmask + p);
    int4   t1 = *(const int4*)(segmask + p + 4);
    float4 e0 = *(const float4*)(edgein + p);
    float4 e1 = *(const float4*)(edgein + p + 4);
    int4   m0 = *(const int4*)(emask + p);
    int4   m1 = *(const int4*)(emask + p + 4);

    int   tv[PPT] = {t0.x, t0.y, t0.z, t0.w, t1.x, t1.y, t1.z, t1.w};
    float ev[PPT] = {e0.x, e0.y, e0.z, e0.w, e1.x, e1.y, e1.z, e1.w};
    int   mv[PPT] = {m0.x, m0.y, m0.z, m0.w, m1.x, m1.y, m1.z, m1.w};

    int tcls[PPT];
#pragma unroll
    for (int i = 0; i < PPT; i++) tcls[i] = min(max(tv[i], 0), NCLS - 1);

    // ---- channel sweep: online sum-exp + target-logit select ----
    const float* sp = segin + (size_t)n * (size_t)NCLS * (size_t)HWPIX + (size_t)local;

    float s[PPT], xt[PPT];
#pragma unroll
    for (int i = 0; i < PPT; i++) { s[i] = 0.f; xt[i] = 0.f; }

#pragma unroll
    for (int c0 = 0; c0 < NCLS; c0 += 4) {
        float4 a[4][2];
#pragma unroll
        for (int j = 0; j < 4; j++) {
            int c = c0 + j;
            if (c < NCLS) {
                a[j][0] = *(const float4*)(sp + (size_t)c * HWPIX);
                a[j][1] = *(const float4*)(sp + (size_t)c * HWPIX + 4);
            }
        }
#pragma unroll
        for (int j = 0; j < 4; j++) {
            int c = c0 + j;
            if (c < NCLS) {
                float xv[PPT] = {a[j][0].x, a[j][0].y, a[j][0].z, a[j][0].w,
                                 a[j][1].x, a[j][1].y, a[j][1].z, a[j][1].w};
#pragma unroll
                for (int i = 0; i < PPT; i++) {
                    s[i] += __expf(xv[i]);
                    xt[i] = (c == tcls[i]) ? xv[i] : xt[i];
                }
            }
        }
    }

    // ---- per-pixel nll, att flag, BCE ----
    float nll[PPT], nllA[PPT];
    unsigned addC[PPT];
    int ec[PPT];
    float bce_p = 0.f, bce_n = 0.f;
    unsigned pn = 0;                              // pos lo16, neg hi16
#pragma unroll
    for (int i = 0; i < PPT; i++) {
        nll[i] = __logf(s[i]) - xt[i];            // -log_softmax[target]
        bool v   = (tv[i] != IGN);
        bool att = v && (ev[i] > EDGE_T);
        ec[i]   = v ? tcls[i] : 255;
        nllA[i] = att ? nll[i] : 0.f;
        addC[i] = att ? 0x10001u : 1u;

        float xx = ev[i];
        float b  = fmaxf(xx, 0.f) - xx * (float)mv[i] + log1pf(__expf(-fabsf(xx)));
        if (mv[i] == 1) { bce_p += b; pn += 1u; }
        else if (mv[i] == 0) { bce_n += b; pn += 0x10000u; }
    }

    // ---- per-class register select + warp/block reduction ----
    __shared__ float sh_ss[NCLS][8];
    __shared__ float sh_sa[NCLS][8];
    __shared__ unsigned sh_cc[NCLS][8];
    __shared__ float sh_bp[8], sh_bn[8];
    __shared__ unsigned sh_pn[8];

#pragma unroll
    for (int c = 0; c < NCLS; c++) {
        float ss = 0.f, sa = 0.f;
        unsigned cc = 0u;
#pragma unroll
        for (int i = 0; i < PPT; i++) {
            if (ec[i] == c) { ss += nll[i]; sa += nllA[i]; cc += addC[i]; }
        }
        for (int o = 16; o; o >>= 1) {
            ss += __shfl_down_sync(0xffffffffu, ss, o);
            sa += __shfl_down_sync(0xffffffffu, sa, o);
        }
        cc = __reduce_add_sync(0xffffffffu, cc);
        if (lid == 0) { sh_ss[c][wid] = ss; sh_sa[c][wid] = sa; sh_cc[c][wid] = cc; }
    }
    for (int o = 16; o; o >>= 1) {
        bce_p += __shfl_down_sync(0xffffffffu, bce_p, o);
        bce_n += __shfl_down_sync(0xffffffffu, bce_n, o);
    }
    pn = __reduce_add_sync(0xffffffffu, pn);
    if (lid == 0) { sh_bp[wid] = bce_p; sh_bn[wid] = bce_n; sh_pn[wid] = pn; }
    __syncthreads();

    if (tid < NCLS) {
        float ss = 0.f, sa = 0.f; unsigned cc = 0u;
#pragma unroll
        for (int w = 0; w < 8; w++) { ss += sh_ss[tid][w]; sa += sh_sa[tid][w]; cc += sh_cc[tid][w]; }
        int gi = n * NCLS + tid;
        atomicAdd(&g_seg_sum[gi], (double)ss);
        atomicAdd(&g_att_sum[gi], (double)sa);
        atomicAdd(&g_seg_cnt[gi], (int)(cc & 0xffffu));
        atomicAdd(&g_att_cnt[gi], (int)(cc >> 16));
    } else if (tid == 32) {
        float bp = 0.f, bn = 0.f; unsigned c = 0u;
#pragma unroll
        for (int w = 0; w < 8; w++) { bp += sh_bp[w]; bn += sh_bn[w]; c += sh_pn[w]; }
        atomicAdd(&g_bce_pos, (double)bp);
        atomicAdd(&g_bce_neg, (double)bn);
        atomicAdd(&g_pos, (int)(c & 0xffffu));
        atomicAdd(&g_neg, (int)(c >> 16));
    }

    // ---- fan-in: last block finalizes ----
    __syncthreads();
    __shared__ unsigned s_last;
    if (tid == 0) {
        __threadfence();
        s_last = (atomicAdd(&g_done, 1u) == GRID - 1u);
    }
    __syncthreads();
    if (!s_last) return;
    __threadfence();   // acquire: make all blocks' g_* writes visible

    // ---------------- finalize (parallel across 76 threads) ----------------
    __shared__ double f_ss[NIMG * NCLS], f_as[NIMG * NCLS];
    __shared__ int    f_sc[NIMG * NCLS], f_ac[NIMG * NCLS];
    __shared__ double f_rs[NIMG], f_ra[NIMG];       // reciprocals of per-image totals
    __shared__ double f_t[NIMG * NCLS][4];          // {snum,sden,anum,aden} terms
    __shared__ double f_img[NIMG][2];
    __shared__ double f_bce[2];
    __shared__ int    f_pn[2];

    if (tid < NIMG * NCLS) {
        f_ss[tid] = g_seg_sum[tid];
        f_as[tid] = g_att_sum[tid];
        f_sc[tid] = g_seg_cnt[tid];
        f_ac[tid] = g_att_cnt[tid];
    }
    if (tid == 96) { f_bce[0] = g_bce_pos; f_bce[1] = g_bce_neg; }
    if (tid == 97) { f_pn[0] = g_pos; f_pn[1] = g_neg; }
    __syncthreads();

    if (tid < NIMG) {                   // totals + single reciprocal per image
        int ssum = 0, asum = 0;
#pragma unroll
        for (int c = 0; c < NCLS; c++) { ssum += f_sc[tid * NCLS + c]; asum += f_ac[tid * NCLS + c]; }
        f_rs[tid] = 1.0 / (double)ssum;
        f_ra[tid] = 1.0 / (double)asum;
    }
    __syncthreads();

    if (tid < NIMG * NCLS) {            // per-(image,class) weighted terms, no divides
        int nimg = tid / NCLS;
        int sc = f_sc[tid], ac = f_ac[tid];
        double ws = sc ? (2.0 - (double)sc * f_rs[nimg]) : 1.0;
        double wa = ac ? (2.0 - (double)ac * f_ra[nimg]) : 1.0;
        f_t[tid][0] = ws * f_ss[tid];
        f_t[tid][1] = ws * (double)sc;
        f_t[tid][2] = wa * f_as[tid];
        f_t[tid][3] = wa * (double)ac;
    }
    __syncthreads();

    if (tid < NIMG) {                   // per-image reduce + 2 divides
        double sn = 0, sd = 0, an = 0, ad = 0;
#pragma unroll
        for (int c = 0; c < NCLS; c++) {
            sn += f_t[tid * NCLS + c][0]; sd += f_t[tid * NCLS + c][1];
            an += f_t[tid * NCLS + c][2]; ad += f_t[tid * NCLS + c][3];
        }
        f_img[tid][0] = sn / sd;
        f_img[tid][1] = an / ad;
    }
    __syncthreads();

    if (tid == 0) {
        double segl = 0.0, attl = 0.0;
#pragma unroll
        for (int nn2 = 0; nn2 < NIMG; nn2++) { segl += f_img[nn2][0]; attl += f_img[nn2][1]; }
        double pp = (double)f_pn[0], nng = (double)f_pn[1], sm = pp + nng;
        double bce = ((nng / sm) * f_bce[0] + (pp / sm) * f_bce[1]) / (double)NTOT;
        out[0] = (float)(segl + 0.3 * bce + 0.1 * attl);
    }

    // reset scratch for next graph replay
    if (tid < NIMG * NCLS) {
        g_seg_sum[tid] = 0.0; g_att_sum[tid] = 0.0;
        g_seg_cnt[tid] = 0;   g_att_cnt[tid] = 0;
    }
    if (tid == 96) { g_bce_pos = 0.0; g_bce_neg = 0.0; }
    if (tid == 97) { g_pos = 0; g_neg = 0; }
    if (tid == 98) g_done = 0u;
}

extern "C" void kernel_launch(void* const* d_in, const int* in_sizes, int n_in,
                              void* d_out, int out_size) {
    const float* segin   = (const float*)d_in[0];
    const float* edgein  = (const float*)d_in[1];
    const int*   segmask = (const int*)d_in[2];
    const int*   emask   = (const int*)d_in[3];

    k_fused<<<GRID, TPB>>>(segin, edgein, segmask, emask, (float*)d_out);
}